// round 14
// baseline (speedup 1.0000x reference)
#include <cuda_runtime.h>
#include <cuda_fp16.h>
#include <cstdint>
#include <math.h>

// Problem shape (fixed by setup_inputs)
constexpr int Bc  = 2;
constexpr int Sc  = 2048;
constexpr int Dc  = 1024;
constexpr int Hc  = 8;
constexpr int HDc = 128;

constexpr float L2E = 1.4426950408889634f;

// Scratch (no allocations allowed)
__device__ __align__(256) float    g_inv_dsq[(size_t)Sc * Sc];       // 16 MB
__device__ __align__(256) float    g_masses[Bc * Hc * Sc];           // 128 KB
__device__ __align__(256) float    g_rowmax[Bc * Hc * Sc];           // 128 KB
__device__ __align__(256) __half   g_xh[(size_t)Bc * Sc * Dc];       // 8 MB   x fp16
__device__ __align__(256) __half   g_vwh[(size_t)Dc * Dc];           // 2 MB   v_w fp16
__device__ __align__(256) __half   g_owh[(size_t)Dc * Dc];           // 2 MB   out_w fp16
__device__ __align__(256) float    g_v[(size_t)Bc * Sc * Dc];        // 32 MB
__device__ __align__(256) __half   g_vTh[(size_t)Bc * Hc * HDc * Sc];// 16 MB [bh][d][k] fp16
__device__ __align__(256) __half   g_hoh[(size_t)Bc * Sc * Dc];      // 8 MB  head_out fp16

// ---------------------------------------------------------------------------
// helpers
// ---------------------------------------------------------------------------
__device__ __forceinline__ uint32_t smem_u32(const void* p) {
    uint32_t a;
    asm("{ .reg .u64 t; cvta.to.shared.u64 t, %1; cvt.u32.u64 %0, t; }"
        : "=r"(a) : "l"(p));
    return a;
}
__device__ __forceinline__ float ex2(float x) {
    float y;
    asm("ex2.approx.f32 %0, %1;" : "=f"(y) : "f"(x));
    return y;
}
__device__ __forceinline__ float rcp_approx(float x) {
    float y;
    asm("rcp.approx.f32 %0, %1;" : "=f"(y) : "f"(x));
    return y;
}
__device__ __forceinline__ void mma_m16n8k16f16(float c[4], const uint32_t a[4],
                                                const uint32_t b[2]) {
    asm volatile(
        "mma.sync.aligned.m16n8k16.row.col.f32.f16.f16.f32 "
        "{%0,%1,%2,%3}, {%4,%5,%6,%7}, {%8,%9}, {%0,%1,%2,%3};"
        : "+f"(c[0]), "+f"(c[1]), "+f"(c[2]), "+f"(c[3])
        : "r"(a[0]), "r"(a[1]), "r"(a[2]), "r"(a[3]), "r"(b[0]), "r"(b[1]));
}
__device__ __forceinline__ void ldsm4(uint32_t& r0, uint32_t& r1, uint32_t& r2,
                                      uint32_t& r3, uint32_t addr) {
    asm volatile("ldmatrix.sync.aligned.m8n8.x4.shared.b16 {%0,%1,%2,%3}, [%4];"
                 : "=r"(r0), "=r"(r1), "=r"(r2), "=r"(r3) : "r"(addr));
}
__device__ __forceinline__ void cp16(uint32_t dst, const void* src) {
    asm volatile("cp.async.cg.shared.global [%0], [%1], 16;" :: "r"(dst), "l"(src));
}
#define CP_COMMIT() asm volatile("cp.async.commit_group;" ::: "memory")
#define CP_WAIT1()  asm volatile("cp.async.wait_group 1;" ::: "memory")

__device__ __forceinline__ uint32_t h2u(__half2 h) { return *(uint32_t*)&h; }

constexpr int SH    = 40;          // fp16 padded row stride (halves) = 80B
constexpr int HTILE = 128 * SH;    // halves per 128x32 fp16 tile

// ---------------------------------------------------------------------------
// 1) FUSED dist + rowmax: one block per q row.
//    Computes iv[q][k] for all k (8 per thread), writes g_inv_dsq, then
//    reduces rowmax[bh][q] = min(mq * max_k(mk*iv), 50) for all 16 bh
//    from the in-register iv values (no 16 MB re-read, no second launch).
// ---------------------------------------------------------------------------
__global__ __launch_bounds__(256) void dist_rowmax_kernel(const float* __restrict__ pos) {
    __shared__ float sred[16][9];
    int q = blockIdx.x;
    int tid = threadIdx.x, lane = tid & 31, wrp = tid >> 5;
    float pq[8];
#pragma unroll
    for (int j = 0; j < 8; j++) pq[j] = __ldg(&pos[q * 8 + j]);
    int k0 = tid * 8;
    float ivv[8];
#pragma unroll
    for (int kk = 0; kk < 8; kk++) {
        float acc = 1e-12f;
#pragma unroll
        for (int j = 0; j < 8; j++) {
            float d = pq[j] - __ldg(&pos[(k0 + kk) * 8 + j]);
            acc = fmaf(d, d, acc);
        }
        float dist = acc * rsqrtf(acc);          // sqrt via MUFU.RSQ
        float s = __sinf(dist);
        dist = dist * fmaf(0.15f, s, 1.0f);
        dist = fmaxf(dist, 0.0f);
        ivv[kk] = rcp_approx(fmaf(dist, dist, 1e-6f));
    }
    float* dst = &g_inv_dsq[(size_t)q * Sc + k0];
    *(float4*)dst       = make_float4(ivv[0], ivv[1], ivv[2], ivv[3]);
    *(float4*)(dst + 4) = make_float4(ivv[4], ivv[5], ivv[6], ivv[7]);

    // rowmax reduction over the locally-held iv values
    float mx[16];
#pragma unroll
    for (int b = 0; b < 16; b++) mx[b] = 0.0f;   // products are > 0
#pragma unroll
    for (int j = 0; j < 2; j++) {
#pragma unroll
        for (int b = 0; b < 16; b++) {
            float4 mk = __ldg((const float4*)&g_masses[b * Sc + k0 + j * 4]);
            mx[b] = fmaxf(mx[b],
                          fmaxf(fmaxf(mk.x * ivv[j * 4 + 0], mk.y * ivv[j * 4 + 1]),
                                fmaxf(mk.z * ivv[j * 4 + 2], mk.w * ivv[j * 4 + 3])));
        }
    }
#pragma unroll
    for (int b = 0; b < 16; b++) {
#pragma unroll
        for (int o = 16; o; o >>= 1)
            mx[b] = fmaxf(mx[b], __shfl_xor_sync(0xffffffffu, mx[b], o));
    }
    if (lane == 0)
#pragma unroll
        for (int b = 0; b < 16; b++) sred[b][wrp] = mx[b];
    __syncthreads();
    if (tid < 16) {
        float m = sred[tid][0];
#pragma unroll
        for (int i = 1; i < 8; i++) m = fmaxf(m, sred[tid][i]);
        float mq = g_masses[tid * Sc + q];
        g_rowmax[tid * Sc + q] = fminf(mq * m, 50.0f);
    }
}

// ---------------------------------------------------------------------------
// 2) masses[bh][s] = sigmoid( x[b,s,h*128:] . mass_w[h,:] )
// ---------------------------------------------------------------------------
__global__ __launch_bounds__(256) void masses_kernel(const float* __restrict__ x,
                                                     const float* __restrict__ mw) {
    int gw   = blockIdx.x * 8 + (threadIdx.x >> 5);
    int lane = threadIdx.x & 31;
    int bh = gw / Sc;
    int s  = gw % Sc;
    int b = bh >> 3, h = bh & 7;
    const float4* xp = (const float4*)(x + ((size_t)(b * Sc + s)) * Dc + h * HDc);
    const float4* wp = (const float4*)(mw + h * HDc);
    float4 a = xp[lane];
    float4 w = wp[lane];
    float dot = a.x * w.x + a.y * w.y + a.z * w.z + a.w * w.w;
#pragma unroll
    for (int o = 16; o; o >>= 1) dot += __shfl_xor_sync(0xffffffffu, dot, o);
    if (lane == 0) g_masses[bh * Sc + s] = 1.0f / (1.0f + __expf(-dot));
}

// ---------------------------------------------------------------------------
// 3) f32 -> fp16 conversion pass
// ---------------------------------------------------------------------------
__global__ __launch_bounds__(256) void cvt16_kernel(const float* __restrict__ in,
                                                    __half* __restrict__ out, int n4) {
    int i = blockIdx.x * blockDim.x + threadIdx.x;
    if (i < n4) {
        float4 v = __ldg((const float4*)in + i);
        uint2 u;
        u.x = h2u(__floats2half2_rn(v.x, v.y));
        u.y = h2u(__floats2half2_rn(v.z, v.w));
        ((uint2*)out)[i] = u;
    }
}

// ---------------------------------------------------------------------------
// 4/7) fp16 GEMM (fp32 accum): C[M,N] = A[M,K] * B[N,K]^T
// ---------------------------------------------------------------------------
__global__ __launch_bounds__(256, 2) void gemm_fp16(const __half* __restrict__ A,
                                                    const __half* __restrict__ B,
                                                    float* __restrict__ C,
                                                    int N, int K) {
    extern __shared__ uint32_t sm[];
    int tid = threadIdx.x, lane = tid & 31, wid = tid >> 5;
    int wm = wid & 3, wn = wid >> 2;
    int row0 = blockIdx.y * 128, col0 = blockIdx.x * 128;
    int fr = tid >> 1;
    int fc = (tid & 1) * 16;
    uint32_t sbase = smem_u32(sm);

    int r = lane & 7, m = lane >> 3;
    int aoff[2], boff[4];
#pragma unroll
    for (int t = 0; t < 2; t++)
        aoff[t] = (wm * 32 + t * 16 + (m & 1) * 8 + r) * SH + (m >> 1) * 8;
#pragma unroll
    for (int j = 0; j < 4; j++)
        boff[j] = (wn * 64 + j * 16 + (m & 1) * 8 + r) * SH + (m >> 1) * 8;

    float c[2][8][4] = {};
    int nkt = K / 32;

    const __half* Ap = A + (size_t)(row0 + fr) * K + fc;
    const __half* Bp = B + (size_t)(col0 + fr) * K + fc;

#pragma unroll
    for (int s = 0; s < 2; s++) {
        uint32_t ast = sbase + (s * 2 * HTILE) * 2;
        uint32_t bst = ast + HTILE * 2;
        cp16(ast + (fr * SH + fc) * 2,     Ap + s * 32);
        cp16(ast + (fr * SH + fc + 8) * 2, Ap + s * 32 + 8);
        cp16(bst + (fr * SH + fc) * 2,     Bp + s * 32);
        cp16(bst + (fr * SH + fc + 8) * 2, Bp + s * 32 + 8);
        CP_COMMIT();
    }

    for (int kt = 0; kt < nkt; kt++) {
        CP_WAIT1();
        __syncthreads();
        if (kt + 2 < nkt) {
            int s = (kt + 2) % 3, k0 = (kt + 2) * 32;
            uint32_t ast = sbase + (s * 2 * HTILE) * 2;
            uint32_t bst = ast + HTILE * 2;
            cp16(ast + (fr * SH + fc) * 2,     Ap + k0);
            cp16(ast + (fr * SH + fc + 8) * 2, Ap + k0 + 8);
            cp16(bst + (fr * SH + fc) * 2,     Bp + k0);
            cp16(bst + (fr * SH + fc + 8) * 2, Bp + k0 + 8);
        }
        CP_COMMIT();
        uint32_t sa = sbase + ((kt % 3) * 2 * HTILE) * 2;
        uint32_t sb = sa + HTILE * 2;
#pragma unroll
        for (int ks = 0; ks < 2; ks++) {
            uint32_t a[2][4], bq[4][4];
#pragma unroll
            for (int t = 0; t < 2; t++)
                ldsm4(a[t][0], a[t][1], a[t][2], a[t][3], sa + (aoff[t] + ks * 16) * 2);
#pragma unroll
            for (int j = 0; j < 4; j++)
                ldsm4(bq[j][0], bq[j][1], bq[j][2], bq[j][3], sb + (boff[j] + ks * 16) * 2);
#pragma unroll
            for (int t = 0; t < 2; t++)
#pragma unroll
                for (int j = 0; j < 4; j++) {
                    uint32_t b0[2] = {bq[j][0], bq[j][2]};
                    uint32_t b1[2] = {bq[j][1], bq[j][3]};
                    mma_m16n8k16f16(c[t][2 * j],     a[t], b0);
                    mma_m16n8k16f16(c[t][2 * j + 1], a[t], b1);
                }
        }
    }

#pragma unroll
    for (int t = 0; t < 2; t++) {
        int row = row0 + wm * 32 + t * 16 + (lane >> 2);
#pragma unroll
        for (int n = 0; n < 8; n++) {
            int col = col0 + wn * 64 + n * 8 + (lane & 3) * 2;
            *(float2*)&C[(size_t)row * N + col]       = make_float2(c[t][n][0], c[t][n][1]);
            *(float2*)&C[(size_t)(row + 8) * N + col] = make_float2(c[t][n][2], c[t][n][3]);
        }
    }
}

// ---------------------------------------------------------------------------
// 5) transpose v -> g_vTh[bh][d][k]  (fp16, k contiguous)
// ---------------------------------------------------------------------------
__global__ void transpose_v() {
    __shared__ float t[32][33];
    int k0 = blockIdx.x * 32, d0 = blockIdx.y * 32, bh = blockIdx.z;
    int b = bh >> 3, h = bh & 7;
    int tx = threadIdx.x, ty = threadIdx.y;
    const float* src = g_v + (size_t)b * Sc * Dc + h * HDc;
#pragma unroll
    for (int i = 0; i < 32; i += 8)
        t[ty + i][tx] = src[(size_t)(k0 + ty + i) * Dc + d0 + tx];
    __syncthreads();
    __half* dst = g_vTh + (size_t)bh * HDc * Sc;
#pragma unroll
    for (int i = 0; i < 32; i += 8)
        dst[(size_t)(d0 + ty + i) * Sc + k0 + tx] = __float2half_rn(t[tx][ty + i]);
}

// ---------------------------------------------------------------------------
// score emit: 4 weights -> 2 packed fp16x2
// ---------------------------------------------------------------------------
__device__ __forceinline__ void emit4(float4 mk, float4 iv, float a, float nb,
                                      float cap, uint32_t& lo, uint32_t& hi) {
    float w0 = ex2(fminf(fmaf(mk.x * iv.x, a, nb), cap));
    float w1 = ex2(fminf(fmaf(mk.y * iv.y, a, nb), cap));
    float w2 = ex2(fminf(fmaf(mk.z * iv.z, a, nb), cap));
    float w3 = ex2(fminf(fmaf(mk.w * iv.w, a, nb), cap));
    lo = h2u(__floats2half2_rn(w0, w1));
    hi = h2u(__floats2half2_rn(w2, w3));
}

// ---------------------------------------------------------------------------
// 6) Fused attention, fp16 MMA (fp32 accum). q-tile 128, 256 threads,
//    2 CTAs/SM. Row sums via ones-column MMA. Masses row staged in SMEM.
// ---------------------------------------------------------------------------
__global__ __launch_bounds__(256, 2) void attn_fp16() {
    extern __shared__ uint32_t sm[];
    __half* Ws = (__half*)sm;                      // 2 W tiles then 3 V tiles
    float* mks = (float*)(sm + (5 * HTILE * 2) / 4);  // masses row, 2048 floats

    int tid = threadIdx.x, lane = tid & 31, wid = tid >> 5;
    int wm = wid & 3, wn = wid >> 2;
    int bh = blockIdx.y;
    int b = bh >> 3, h = bh & 7;
    int q0 = blockIdx.x * 128;
    int fr = tid >> 1, fc = (tid & 1) * 16;
    uint32_t sbase = smem_u32(sm);
    uint32_t vbase = sbase + 2 * HTILE * 2;

    int r = lane & 7, m = lane >> 3;
    int aoff[2], boff[4];
#pragma unroll
    for (int t = 0; t < 2; t++)
        aoff[t] = (wm * 32 + t * 16 + (m & 1) * 8 + r) * SH + (m >> 1) * 8;
#pragma unroll
    for (int j = 0; j < 4; j++)
        boff[j] = (wn * 64 + j * 16 + (m & 1) * 8 + r) * SH + (m >> 1) * 8;

    int myq = tid >> 1;
    int kh  = (tid & 1) * 16;
    const float* mrow = g_masses + bh * Sc;
    const float* drow = g_inv_dsq + (size_t)(q0 + myq) * Sc;
    const __half* vt  = g_vTh + (size_t)bh * HDc * Sc + (size_t)fr * Sc + fc;
    float mq = mrow[q0 + myq];
    float rm = g_rowmax[bh * Sc + q0 + myq];
    float sa_mul = mq * L2E;
    float nb = -rm * L2E;
    float cap = (50.0f - rm) * L2E;

    float c[2][8][4] = {};
    float csum[2][4] = {};
    const uint32_t bones[2] = {0x3C003C00u, 0x3C003C00u};  // half2(1,1) x2
    constexpr int NKT = Sc / 32;

    // prologue: V stages 0,1 async
#pragma unroll
    for (int s = 0; s < 2; s++) {
        uint32_t vst = vbase + s * HTILE * 2;
        cp16(vst + (fr * SH + fc) * 2,     vt + s * 32);
        cp16(vst + (fr * SH + fc + 8) * 2, vt + s * 32 + 8);
        CP_COMMIT();
    }
    // stage masses row into smem (512 float4 / 256 threads)
#pragma unroll
    for (int i = 0; i < 2; i++)
        ((float4*)mks)[tid + i * 256] = __ldg((const float4*)mrow + tid + i * 256);
    __syncthreads();

    // scores tile 0 into W buf 0
    float4 iv[4];
#pragma unroll
    for (int j = 0; j < 4; j++) iv[j] = __ldg((const float4*)&drow[kh + j * 4]);
    {
        __half* wrow = Ws + myq * SH + kh;
        uint32_t wb[8];
#pragma unroll
        for (int j = 0; j < 4; j++) {
            float4 mk = *(const float4*)&mks[kh + j * 4];
            emit4(mk, iv[j], sa_mul, nb, cap, wb[2 * j], wb[2 * j + 1]);
        }
        *(uint4*)wrow       = make_uint4(wb[0], wb[1], wb[2], wb[3]);
        *(uint4*)(wrow + 8) = make_uint4(wb[4], wb[5], wb[6], wb[7]);
    }
#pragma unroll
    for (int j = 0; j < 4; j++) iv[j] = __ldg((const float4*)&drow[32 + kh + j * 4]);

    for (int kt = 0; kt < NKT; kt++) {
        CP_WAIT1();
        __syncthreads();
        if (kt + 2 < NKT) {
            int s = (kt + 2) % 3, k0 = (kt + 2) * 32;
            uint32_t vst = vbase + s * HTILE * 2;
            cp16(vst + (fr * SH + fc) * 2,     vt + k0);
            cp16(vst + (fr * SH + fc + 8) * 2, vt + k0 + 8);
        }
        CP_COMMIT();
        if (kt + 1 < NKT) {
            int k0n = (kt + 1) * 32;
            __half* wrow = Ws + ((kt + 1) & 1) * HTILE + myq * SH + kh;
            uint32_t wb[8];
#pragma unroll
            for (int j = 0; j < 4; j++) {
                float4 mk = *(const float4*)&mks[k0n + kh + j * 4];
                emit4(mk, iv[j], sa_mul, nb, cap, wb[2 * j], wb[2 * j + 1]);
            }
            *(uint4*)wrow       = make_uint4(wb[0], wb[1], wb[2], wb[3]);
            *(uint4*)(wrow + 8) = make_uint4(wb[4], wb[5], wb[6], wb[7]);
            if (kt + 2 < NKT) {
                int k0p = (kt + 2) * 32;
#pragma unroll
                for (int j = 0; j < 4; j++)
                    iv[j] = __ldg((const float4*)&drow[k0p + kh + j * 4]);
            }
        }
        uint32_t sa = sbase + ((kt & 1) * HTILE) * 2;
        uint32_t sb = vbase + ((kt % 3) * HTILE) * 2;
#pragma unroll
        for (int ks = 0; ks < 2; ks++) {
            uint32_t a[2][4], bq[4][4];
#pragma unroll
            for (int t = 0; t < 2; t++)
                ldsm4(a[t][0], a[t][1], a[t][2], a[t][3], sa + (aoff[t] + ks * 16) * 2);
#pragma unroll
            for (int j = 0; j < 4; j++)
                ldsm4(bq[j][0], bq[j][1], bq[j][2], bq[j][3], sb + (boff[j] + ks * 16) * 2);
#pragma unroll
            for (int t = 0; t < 2; t++) {
#pragma unroll
                for (int j = 0; j < 4; j++) {
                    uint32_t b0[2] = {bq[j][0], bq[j][2]};
                    uint32_t b1[2] = {bq[j][1], bq[j][3]};
                    mma_m16n8k16f16(c[t][2 * j],     a[t], b0);
                    mma_m16n8k16f16(c[t][2 * j + 1], a[t], b1);
                }
                mma_m16n8k16f16(csum[t], a[t], bones);   // row sums
            }
        }
    }

    // epilogue: every column of csum[t] equals the row sum
#pragma unroll
    for (int t = 0; t < 2; t++) {
        int rl = wm * 32 + t * 16 + (lane >> 2);
        float r0 = 1.0f / csum[t][0];
        float r1 = 1.0f / csum[t][2];
        __half* o0 = g_hoh + ((size_t)(b * Sc + q0 + rl)) * Dc + h * HDc;
        __half* o1 = g_hoh + ((size_t)(b * Sc + q0 + rl + 8)) * Dc + h * HDc;
#pragma unroll
        for (int n = 0; n < 8; n++) {
            int col = wn * 64 + n * 8 + (lane & 3) * 2;
            *(__half2*)&o0[col] = __floats2half2_rn(c[t][n][0] * r0, c[t][n][1] * r0);
            *(__half2*)&o1[col] = __floats2half2_rn(c[t][n][2] * r1, c[t][n][3] * r1);
        }
    }
}

// ---------------------------------------------------------------------------
extern "C" void kernel_launch(void* const* d_in, const int* in_sizes, int n_in,
                              void* d_out, int out_size) {
    const float* x      = (const float*)d_in[0];
    const float* mass_w = (const float*)d_in[1];
    const float* v_w    = (const float*)d_in[2];
    const float* out_w  = (const float*)d_in[3];
    const float* pos    = (const float*)d_in[4];
    float* out = (float*)d_out;

    void *pxh = nullptr, *pvwh = nullptr, *powh = nullptr, *pv = nullptr, *phoh = nullptr;
    cudaGetSymbolAddress(&pxh,  g_xh);
    cudaGetSymbolAddress(&pvwh, g_vwh);
    cudaGetSymbolAddress(&powh, g_owh);
    cudaGetSymbolAddress(&pv,   g_v);
    cudaGetSymbolAddress(&phoh, g_hoh);

    const int GEMM_SMEM = 3 * 2 * HTILE * 2;               // 61440 B
    const int ATTN_SMEM = 5 * HTILE * 2 + Sc * 4;          // 59392 B
    cudaFuncSetAttribute(gemm_fp16, cudaFuncAttributeMaxDynamicSharedMemorySize, GEMM_SMEM);
    cudaFuncSetAttribute(attn_fp16, cudaFuncAttributeMaxDynamicSharedMemorySize, ATTN_SMEM);

    // masses BEFORE the fused dist+rowmax (rowmax reads g_masses)
    masses_kernel<<<(Bc * Hc * Sc) / 8, 256>>>(x, mass_w);
    dist_rowmax_kernel<<<Sc, 256>>>(pos);
    cvt16_kernel<<<(Bc * Sc * Dc / 4 + 255) / 256, 256>>>(x, (__half*)pxh, Bc * Sc * Dc / 4);
    cvt16_kernel<<<(Dc * Dc / 4 + 255) / 256, 256>>>(v_w, (__half*)pvwh, Dc * Dc / 4);
    cvt16_kernel<<<(Dc * Dc / 4 + 255) / 256, 256>>>(out_w, (__half*)powh, Dc * Dc / 4);

    gemm_fp16<<<dim3(Dc / 128, (Bc * Sc) / 128), 256, GEMM_SMEM>>>(
        (const __half*)pxh, (const __half*)pvwh, (float*)pv, Dc, Dc);
    transpose_v<<<dim3(Sc / 32, HDc / 32, Bc * Hc), dim3(32, 8)>>>();
    attn_fp16<<<dim3(Sc / 128, Bc * Hc), 256, ATTN_SMEM>>>();
    gemm_fp16<<<dim3(Dc / 128, (Bc * Sc) / 128), 256, GEMM_SMEM>>>(
        (const __half*)phoh, (const __half*)powh, out, Dc, Dc);
}

// round 15
// speedup vs baseline: 1.3238x; 1.3238x over previous
#include <cuda_runtime.h>
#include <cuda_fp16.h>
#include <cstdint>
#include <math.h>

// Problem shape (fixed by setup_inputs)
constexpr int Bc  = 2;
constexpr int Sc  = 2048;
constexpr int Dc  = 1024;
constexpr int Hc  = 8;
constexpr int HDc = 128;

constexpr float L2E = 1.4426950408889634f;

// Scratch (no allocations allowed)
__device__ __align__(256) float    g_inv_dsq[(size_t)Sc * Sc];       // 16 MB
__device__ __align__(256) float    g_masses[Bc * Hc * Sc];           // 128 KB
__device__ __align__(256) float    g_rowmax[Bc * Hc * Sc];           // 128 KB
__device__ __align__(256) __half   g_xh[(size_t)Bc * Sc * Dc];       // 8 MB   x fp16
__device__ __align__(256) __half   g_vwh[(size_t)Dc * Dc];           // 2 MB   v_w fp16
__device__ __align__(256) __half   g_owh[(size_t)Dc * Dc];           // 2 MB   out_w fp16
__device__ __align__(256) __half   g_vh[(size_t)Bc * Sc * Dc];       // 8 MB   v fp16 [seq][D]
__device__ __align__(256) __half   g_vTh[(size_t)Bc * Hc * HDc * Sc];// 16 MB [bh][d][k] fp16
__device__ __align__(256) __half   g_hoh[(size_t)Bc * Sc * Dc];      // 8 MB  head_out fp16

// ---------------------------------------------------------------------------
// helpers
// ---------------------------------------------------------------------------
__device__ __forceinline__ uint32_t smem_u32(const void* p) {
    uint32_t a;
    asm("{ .reg .u64 t; cvta.to.shared.u64 t, %1; cvt.u32.u64 %0, t; }"
        : "=r"(a) : "l"(p));
    return a;
}
__device__ __forceinline__ float ex2(float x) {
    float y;
    asm("ex2.approx.f32 %0, %1;" : "=f"(y) : "f"(x));
    return y;
}
__device__ __forceinline__ float rcp_approx(float x) {
    float y;
    asm("rcp.approx.f32 %0, %1;" : "=f"(y) : "f"(x));
    return y;
}
__device__ __forceinline__ void mma_m16n8k16f16(float c[4], const uint32_t a[4],
                                                const uint32_t b[2]) {
    asm volatile(
        "mma.sync.aligned.m16n8k16.row.col.f32.f16.f16.f32 "
        "{%0,%1,%2,%3}, {%4,%5,%6,%7}, {%8,%9}, {%0,%1,%2,%3};"
        : "+f"(c[0]), "+f"(c[1]), "+f"(c[2]), "+f"(c[3])
        : "r"(a[0]), "r"(a[1]), "r"(a[2]), "r"(a[3]), "r"(b[0]), "r"(b[1]));
}
__device__ __forceinline__ void ldsm4(uint32_t& r0, uint32_t& r1, uint32_t& r2,
                                      uint32_t& r3, uint32_t addr) {
    asm volatile("ldmatrix.sync.aligned.m8n8.x4.shared.b16 {%0,%1,%2,%3}, [%4];"
                 : "=r"(r0), "=r"(r1), "=r"(r2), "=r"(r3) : "r"(addr));
}
__device__ __forceinline__ void cp16(uint32_t dst, const void* src) {
    asm volatile("cp.async.cg.shared.global [%0], [%1], 16;" :: "r"(dst), "l"(src));
}
#define CP_COMMIT() asm volatile("cp.async.commit_group;" ::: "memory")
#define CP_WAIT1()  asm volatile("cp.async.wait_group 1;" ::: "memory")

__device__ __forceinline__ uint32_t h2u(__half2 h) { return *(uint32_t*)&h; }

__device__ __forceinline__ void st2(float* p, float a, float b) {
    *(float2*)p = make_float2(a, b);
}
__device__ __forceinline__ void st2(__half* p, float a, float b) {
    *(__half2*)p = __floats2half2_rn(a, b);
}

constexpr int SH    = 40;          // fp16 padded row stride (halves) = 80B
constexpr int HTILE = 128 * SH;    // halves per 128x32 fp16 tile

// ---------------------------------------------------------------------------
// 1) inv_dsq[q][k] = 1 / (d'(q,k)^2 + 1e-6)   (approx transcendentals)
// ---------------------------------------------------------------------------
__global__ void dist_kernel(const float* __restrict__ pos) {
    int q = blockIdx.y;
    int k = blockIdx.x * blockDim.x + threadIdx.x;
    float acc = 1e-12f;
#pragma unroll
    for (int j = 0; j < 8; j++) {
        float d = pos[q * 8 + j] - pos[k * 8 + j];
        acc = fmaf(d, d, acc);
    }
    float dist = acc * rsqrtf(acc);              // sqrt via MUFU.RSQ
    float s = __sinf(dist);
    dist = dist * fmaf(0.15f, s, 1.0f);
    dist = fmaxf(dist, 0.0f);
    float dsq = fmaf(dist, dist, 1e-6f);
    g_inv_dsq[(size_t)q * Sc + k] = rcp_approx(dsq);
}

// ---------------------------------------------------------------------------
// 2) masses[bh][s] = sigmoid( x[b,s,h*128:] . mass_w[h,:] )
// ---------------------------------------------------------------------------
__global__ __launch_bounds__(256) void masses_kernel(const float* __restrict__ x,
                                                     const float* __restrict__ mw) {
    int gw   = blockIdx.x * 8 + (threadIdx.x >> 5);
    int lane = threadIdx.x & 31;
    int bh = gw / Sc;
    int s  = gw % Sc;
    int b = bh >> 3, h = bh & 7;
    const float4* xp = (const float4*)(x + ((size_t)(b * Sc + s)) * Dc + h * HDc);
    const float4* wp = (const float4*)(mw + h * HDc);
    float4 a = xp[lane];
    float4 w = wp[lane];
    float dot = a.x * w.x + a.y * w.y + a.z * w.z + a.w * w.w;
#pragma unroll
    for (int o = 16; o; o >>= 1) dot += __shfl_xor_sync(0xffffffffu, dot, o);
    if (lane == 0) g_masses[bh * Sc + s] = 1.0f / (1.0f + __expf(-dot));
}

// ---------------------------------------------------------------------------
// 3) rowmax[bh][q] = min( mq * max_k( mk[k] * inv_dsq[q][k] ), 50 )
// ---------------------------------------------------------------------------
__global__ __launch_bounds__(256) void rowmax_kernel() {
    __shared__ float sred[16][9];
    int q = blockIdx.x;
    int tid = threadIdx.x, lane = tid & 31, wrp = tid >> 5;
    const float* iv = g_inv_dsq + (size_t)q * Sc;
    int k0 = tid * 8;
    float mx[16];
#pragma unroll
    for (int b = 0; b < 16; b++) mx[b] = 0.0f;
#pragma unroll
    for (int j = 0; j < 2; j++) {
        float4 v = __ldg((const float4*)&iv[k0 + j * 4]);
#pragma unroll
        for (int b = 0; b < 16; b++) {
            float4 mk = __ldg((const float4*)&g_masses[b * Sc + k0 + j * 4]);
            mx[b] = fmaxf(mx[b], fmaxf(fmaxf(mk.x * v.x, mk.y * v.y),
                                       fmaxf(mk.z * v.z, mk.w * v.w)));
        }
    }
#pragma unroll
    for (int b = 0; b < 16; b++) {
#pragma unroll
        for (int o = 16; o; o >>= 1)
            mx[b] = fmaxf(mx[b], __shfl_xor_sync(0xffffffffu, mx[b], o));
    }
    if (lane == 0)
#pragma unroll
        for (int b = 0; b < 16; b++) sred[b][wrp] = mx[b];
    __syncthreads();
    if (tid < 16) {
        float m = sred[tid][0];
#pragma unroll
        for (int i = 1; i < 8; i++) m = fmaxf(m, sred[tid][i]);
        float mq = g_masses[tid * Sc + q];
        g_rowmax[tid * Sc + q] = fminf(mq * m, 50.0f);
    }
}

// ---------------------------------------------------------------------------
// 4) FUSED f32 -> fp16 conversion for x, v_w, out_w (one launch)
// ---------------------------------------------------------------------------
constexpr int NB_CX = Bc * Sc * Dc / 4 / 256;  // 4096
constexpr int NB_CW = Dc * Dc / 4 / 256;       // 1024
constexpr int NB_CVT = NB_CX + 2 * NB_CW;      // 6144

__global__ __launch_bounds__(256) void cvt3_kernel(const float* __restrict__ x,
                                                   const float* __restrict__ vw,
                                                   const float* __restrict__ ow) {
    int blk = blockIdx.x;
    const float* src;
    __half* dst;
    if (blk < NB_CX)              { src = x;  dst = g_xh; }
    else if (blk < NB_CX + NB_CW) { src = vw; dst = g_vwh; blk -= NB_CX; }
    else                          { src = ow; dst = g_owh; blk -= NB_CX + NB_CW; }
    int i = blk * 256 + threadIdx.x;
    float4 v = __ldg((const float4*)src + i);
    uint2 u;
    u.x = h2u(__floats2half2_rn(v.x, v.y));
    u.y = h2u(__floats2half2_rn(v.z, v.w));
    ((uint2*)dst)[i] = u;
}

// ---------------------------------------------------------------------------
// 5/8) fp16 GEMM (fp32 accum): C[M,N] = A[M,K] * B[N,K]^T, output fp16/fp32
// ---------------------------------------------------------------------------
template <typename OT>
__global__ __launch_bounds__(256, 2) void gemm_fp16(const __half* __restrict__ A,
                                                    const __half* __restrict__ B,
                                                    OT* __restrict__ C,
                                                    int N, int K) {
    extern __shared__ uint32_t sm[];
    int tid = threadIdx.x, lane = tid & 31, wid = tid >> 5;
    int wm = wid & 3, wn = wid >> 2;
    int row0 = blockIdx.y * 128, col0 = blockIdx.x * 128;
    int fr = tid >> 1;
    int fc = (tid & 1) * 16;
    uint32_t sbase = smem_u32(sm);

    int r = lane & 7, m = lane >> 3;
    int aoff[2], boff[4];
#pragma unroll
    for (int t = 0; t < 2; t++)
        aoff[t] = (wm * 32 + t * 16 + (m & 1) * 8 + r) * SH + (m >> 1) * 8;
#pragma unroll
    for (int j = 0; j < 4; j++)
        boff[j] = (wn * 64 + j * 16 + (m & 1) * 8 + r) * SH + (m >> 1) * 8;

    float c[2][8][4] = {};
    int nkt = K / 32;

    const __half* Ap = A + (size_t)(row0 + fr) * K + fc;
    const __half* Bp = B + (size_t)(col0 + fr) * K + fc;

#pragma unroll
    for (int s = 0; s < 2; s++) {
        uint32_t ast = sbase + (s * 2 * HTILE) * 2;
        uint32_t bst = ast + HTILE * 2;
        cp16(ast + (fr * SH + fc) * 2,     Ap + s * 32);
        cp16(ast + (fr * SH + fc + 8) * 2, Ap + s * 32 + 8);
        cp16(bst + (fr * SH + fc) * 2,     Bp + s * 32);
        cp16(bst + (fr * SH + fc + 8) * 2, Bp + s * 32 + 8);
        CP_COMMIT();
    }

    for (int kt = 0; kt < nkt; kt++) {
        CP_WAIT1();
        __syncthreads();
        if (kt + 2 < nkt) {
            int s = (kt + 2) % 3, k0 = (kt + 2) * 32;
            uint32_t ast = sbase + (s * 2 * HTILE) * 2;
            uint32_t bst = ast + HTILE * 2;
            cp16(ast + (fr * SH + fc) * 2,     Ap + k0);
            cp16(ast + (fr * SH + fc + 8) * 2, Ap + k0 + 8);
            cp16(bst + (fr * SH + fc) * 2,     Bp + k0);
            cp16(bst + (fr * SH + fc + 8) * 2, Bp + k0 + 8);
        }
        CP_COMMIT();
        uint32_t sa = sbase + ((kt % 3) * 2 * HTILE) * 2;
        uint32_t sb = sa + HTILE * 2;
#pragma unroll
        for (int ks = 0; ks < 2; ks++) {
            uint32_t a[2][4], bq[4][4];
#pragma unroll
            for (int t = 0; t < 2; t++)
                ldsm4(a[t][0], a[t][1], a[t][2], a[t][3], sa + (aoff[t] + ks * 16) * 2);
#pragma unroll
            for (int j = 0; j < 4; j++)
                ldsm4(bq[j][0], bq[j][1], bq[j][2], bq[j][3], sb + (boff[j] + ks * 16) * 2);
#pragma unroll
            for (int t = 0; t < 2; t++)
#pragma unroll
                for (int j = 0; j < 4; j++) {
                    uint32_t b0[2] = {bq[j][0], bq[j][2]};
                    uint32_t b1[2] = {bq[j][1], bq[j][3]};
                    mma_m16n8k16f16(c[t][2 * j],     a[t], b0);
                    mma_m16n8k16f16(c[t][2 * j + 1], a[t], b1);
                }
        }
    }

#pragma unroll
    for (int t = 0; t < 2; t++) {
        int row = row0 + wm * 32 + t * 16 + (lane >> 2);
#pragma unroll
        for (int n = 0; n < 8; n++) {
            int col = col0 + wn * 64 + n * 8 + (lane & 3) * 2;
            st2(&C[(size_t)row * N + col],       c[t][n][0], c[t][n][1]);
            st2(&C[(size_t)(row + 8) * N + col], c[t][n][2], c[t][n][3]);
        }
    }
}

// ---------------------------------------------------------------------------
// 6) transpose v (fp16 [seq][D]) -> g_vTh[bh][d][k]  (fp16, k contiguous)
// ---------------------------------------------------------------------------
__global__ void transpose_v() {
    __shared__ float t[32][33];
    int k0 = blockIdx.x * 32, d0 = blockIdx.y * 32, bh = blockIdx.z;
    int b = bh >> 3, h = bh & 7;
    int tx = threadIdx.x, ty = threadIdx.y;
    const __half* src = g_vh + (size_t)b * Sc * Dc + h * HDc;
#pragma unroll
    for (int i = 0; i < 32; i += 8)
        t[ty + i][tx] = __half2float(src[(size_t)(k0 + ty + i) * Dc + d0 + tx]);
    __syncthreads();
    __half* dst = g_vTh + (size_t)bh * HDc * Sc;
#pragma unroll
    for (int i = 0; i < 32; i += 8)
        dst[(size_t)(d0 + ty + i) * Sc + k0 + tx] = __float2half_rn(t[tx][ty + i]);
}

// ---------------------------------------------------------------------------
// score emit: 4 weights -> 2 packed fp16x2
// ---------------------------------------------------------------------------
__device__ __forceinline__ void emit4(float4 mk, float4 iv, float a, float nb,
                                      float cap, uint32_t& lo, uint32_t& hi) {
    float w0 = ex2(fminf(fmaf(mk.x * iv.x, a, nb), cap));
    float w1 = ex2(fminf(fmaf(mk.y * iv.y, a, nb), cap));
    float w2 = ex2(fminf(fmaf(mk.z * iv.z, a, nb), cap));
    float w3 = ex2(fminf(fmaf(mk.w * iv.w, a, nb), cap));
    lo = h2u(__floats2half2_rn(w0, w1));
    hi = h2u(__floats2half2_rn(w2, w3));
}

// ---------------------------------------------------------------------------
// 7) Fused attention, fp16 MMA (fp32 accum). q-tile 128, 256 threads,
//    2 CTAs/SM. Row sums via ones-column MMA. Masses row staged in SMEM.
// ---------------------------------------------------------------------------
__global__ __launch_bounds__(256, 2) void attn_fp16() {
    extern __shared__ uint32_t sm[];
    __half* Ws = (__half*)sm;                      // 2 W tiles then 3 V tiles
    float* mks = (float*)(sm + (5 * HTILE * 2) / 4);  // masses row, 2048 floats

    int tid = threadIdx.x, lane = tid & 31, wid = tid >> 5;
    int wm = wid & 3, wn = wid >> 2;
    int bh = blockIdx.y;
    int b = bh >> 3, h = bh & 7;
    int q0 = blockIdx.x * 128;
    int fr = tid >> 1, fc = (tid & 1) * 16;
    uint32_t sbase = smem_u32(sm);
    uint32_t vbase = sbase + 2 * HTILE * 2;

    int r = lane & 7, m = lane >> 3;
    int aoff[2], boff[4];
#pragma unroll
    for (int t = 0; t < 2; t++)
        aoff[t] = (wm * 32 + t * 16 + (m & 1) * 8 + r) * SH + (m >> 1) * 8;
#pragma unroll
    for (int j = 0; j < 4; j++)
        boff[j] = (wn * 64 + j * 16 + (m & 1) * 8 + r) * SH + (m >> 1) * 8;

    int myq = tid >> 1;
    int kh  = (tid & 1) * 16;
    const float* mrow = g_masses + bh * Sc;
    const float* drow = g_inv_dsq + (size_t)(q0 + myq) * Sc;
    const __half* vt  = g_vTh + (size_t)bh * HDc * Sc + (size_t)fr * Sc + fc;
    float mq = mrow[q0 + myq];
    float rm = g_rowmax[bh * Sc + q0 + myq];
    float sa_mul = mq * L2E;
    float nb = -rm * L2E;
    float cap = (50.0f - rm) * L2E;

    float c[2][8][4] = {};
    float csum[2][4] = {};
    const uint32_t bones[2] = {0x3C003C00u, 0x3C003C00u};  // half2(1,1) x2
    constexpr int NKT = Sc / 32;

    // prologue: V stages 0,1 async
#pragma unroll
    for (int s = 0; s < 2; s++) {
        uint32_t vst = vbase + s * HTILE * 2;
        cp16(vst + (fr * SH + fc) * 2,     vt + s * 32);
        cp16(vst + (fr * SH + fc + 8) * 2, vt + s * 32 + 8);
        CP_COMMIT();
    }
    // stage masses row into smem (512 float4 / 256 threads)
#pragma unroll
    for (int i = 0; i < 2; i++)
        ((float4*)mks)[tid + i * 256] = __ldg((const float4*)mrow + tid + i * 256);
    __syncthreads();

    // scores tile 0 into W buf 0
    float4 iv[4];
#pragma unroll
    for (int j = 0; j < 4; j++) iv[j] = __ldg((const float4*)&drow[kh + j * 4]);
    {
        __half* wrow = Ws + myq * SH + kh;
        uint32_t wb[8];
#pragma unroll
        for (int j = 0; j < 4; j++) {
            float4 mk = *(const float4*)&mks[kh + j * 4];
            emit4(mk, iv[j], sa_mul, nb, cap, wb[2 * j], wb[2 * j + 1]);
        }
        *(uint4*)wrow       = make_uint4(wb[0], wb[1], wb[2], wb[3]);
        *(uint4*)(wrow + 8) = make_uint4(wb[4], wb[5], wb[6], wb[7]);
    }
#pragma unroll
    for (int j = 0; j < 4; j++) iv[j] = __ldg((const float4*)&drow[32 + kh + j * 4]);

    for (int kt = 0; kt < NKT; kt++) {
        CP_WAIT1();
        __syncthreads();
        if (kt + 2 < NKT) {
            int s = (kt + 2) % 3, k0 = (kt + 2) * 32;
            uint32_t vst = vbase + s * HTILE * 2;
            cp16(vst + (fr * SH + fc) * 2,     vt + k0);
            cp16(vst + (fr * SH + fc + 8) * 2, vt + k0 + 8);
        }
        CP_COMMIT();
        if (kt + 1 < NKT) {
            int k0n = (kt + 1) * 32;
            __half* wrow = Ws + ((kt + 1) & 1) * HTILE + myq * SH + kh;
            uint32_t wb[8];
#pragma unroll
            for (int j = 0; j < 4; j++) {
                float4 mk = *(const float4*)&mks[k0n + kh + j * 4];
                emit4(mk, iv[j], sa_mul, nb, cap, wb[2 * j], wb[2 * j + 1]);
            }
            *(uint4*)wrow       = make_uint4(wb[0], wb[1], wb[2], wb[3]);
            *(uint4*)(wrow + 8) = make_uint4(wb[4], wb[5], wb[6], wb[7]);
            if (kt + 2 < NKT) {
                int k0p = (kt + 2) * 32;
#pragma unroll
                for (int j = 0; j < 4; j++)
                    iv[j] = __ldg((const float4*)&drow[k0p + kh + j * 4]);
            }
        }
        uint32_t sa = sbase + ((kt & 1) * HTILE) * 2;
        uint32_t sb = vbase + ((kt % 3) * HTILE) * 2;
#pragma unroll
        for (int ks = 0; ks < 2; ks++) {
            uint32_t a[2][4], bq[4][4];
#pragma unroll
            for (int t = 0; t < 2; t++)
                ldsm4(a[t][0], a[t][1], a[t][2], a[t][3], sa + (aoff[t] + ks * 16) * 2);
#pragma unroll
            for (int j = 0; j < 4; j++)
                ldsm4(bq[j][0], bq[j][1], bq[j][2], bq[j][3], sb + (boff[j] + ks * 16) * 2);
#pragma unroll
            for (int t = 0; t < 2; t++) {
#pragma unroll
                for (int j = 0; j < 4; j++) {
                    uint32_t b0[2] = {bq[j][0], bq[j][2]};
                    uint32_t b1[2] = {bq[j][1], bq[j][3]};
                    mma_m16n8k16f16(c[t][2 * j],     a[t], b0);
                    mma_m16n8k16f16(c[t][2 * j + 1], a[t], b1);
                }
                mma_m16n8k16f16(csum[t], a[t], bones);   // row sums
            }
        }
    }

    // epilogue: every column of csum[t] equals the row sum
#pragma unroll
    for (int t = 0; t < 2; t++) {
        int rl = wm * 32 + t * 16 + (lane >> 2);
        float r0 = 1.0f / csum[t][0];
        float r1 = 1.0f / csum[t][2];
        __half* o0 = g_hoh + ((size_t)(b * Sc + q0 + rl)) * Dc + h * HDc;
        __half* o1 = g_hoh + ((size_t)(b * Sc + q0 + rl + 8)) * Dc + h * HDc;
#pragma unroll
        for (int n = 0; n < 8; n++) {
            int col = wn * 64 + n * 8 + (lane & 3) * 2;
            *(__half2*)&o0[col] = __floats2half2_rn(c[t][n][0] * r0, c[t][n][1] * r0);
            *(__half2*)&o1[col] = __floats2half2_rn(c[t][n][2] * r1, c[t][n][3] * r1);
        }
    }
}

// ---------------------------------------------------------------------------
extern "C" void kernel_launch(void* const* d_in, const int* in_sizes, int n_in,
                              void* d_out, int out_size) {
    const float* x      = (const float*)d_in[0];
    const float* mass_w = (const float*)d_in[1];
    const float* v_w    = (const float*)d_in[2];
    const float* out_w  = (const float*)d_in[3];
    const float* pos    = (const float*)d_in[4];
    float* out = (float*)d_out;

    void *pxh = nullptr, *pvwh = nullptr, *powh = nullptr, *pvh = nullptr, *phoh = nullptr;
    cudaGetSymbolAddress(&pxh,  g_xh);
    cudaGetSymbolAddress(&pvwh, g_vwh);
    cudaGetSymbolAddress(&powh, g_owh);
    cudaGetSymbolAddress(&pvh,  g_vh);
    cudaGetSymbolAddress(&phoh, g_hoh);

    const int GEMM_SMEM = 3 * 2 * HTILE * 2;               // 61440 B
    const int ATTN_SMEM = 5 * HTILE * 2 + Sc * 4;          // 59392 B
    cudaFuncSetAttribute(gemm_fp16<__half>, cudaFuncAttributeMaxDynamicSharedMemorySize, GEMM_SMEM);
    cudaFuncSetAttribute(gemm_fp16<float>,  cudaFuncAttributeMaxDynamicSharedMemorySize, GEMM_SMEM);
    cudaFuncSetAttribute(attn_fp16, cudaFuncAttributeMaxDynamicSharedMemorySize, ATTN_SMEM);

    dist_kernel<<<dim3(Sc / 256, Sc), 256>>>(pos);
    masses_kernel<<<(Bc * Hc * Sc) / 8, 256>>>(x, mass_w);
    rowmax_kernel<<<Sc, 256>>>();
    cvt3_kernel<<<NB_CVT, 256>>>(x, v_w, out_w);

    gemm_fp16<__half><<<dim3(Dc / 128, (Bc * Sc) / 128), 256, GEMM_SMEM>>>(
        (const __half*)pxh, (const __half*)pvwh, (__half*)pvh, Dc, Dc);
    transpose_v<<<dim3(Sc / 32, HDc / 32, Bc * Hc), dim3(32, 8)>>>();
    attn_fp16<<<dim3(Sc / 128, Bc * Hc), 256, ATTN_SMEM>>>();
    gemm_fp16<float><<<dim3(Dc / 128, (Bc * Sc) / 128), 256, GEMM_SMEM>>>(
        (const __half*)phoh, (const __half*)powh, out, Dc, Dc);
}